// round 12
// baseline (speedup 1.0000x reference)
#include <cuda_runtime.h>
#include <cuda_bf16.h>

// Problem shape (fixed by the dataset):
//   x : [16, 512, 64, 64] f32
//   s : [16, 512, 1, 4096] f32
//   z : [16, 1, 512, 1]   f32
//   wq: [1,1,5], wk: [1,1,5], wv: [512,1,3,3]
// Output: out [16,512,64,64], s_new [16,512,1,4096], z_new [16,1,512,1]

#define B 16
#define C 512
#define HW 4096
#define BC (B * C)            // 8192
#define OUT_ELEMS (BC * HW)   // 33554432

__device__ float g_y[BC];
__device__ unsigned g_flag[BC];

__device__ __forceinline__ void st_release_gpu(unsigned* p, unsigned v) {
    asm volatile("st.release.gpu.u32 [%0], %1;" :: "l"(p), "r"(v) : "memory");
}
__device__ __forceinline__ unsigned ld_acquire_gpu(const unsigned* p) {
    unsigned v;
    asm volatile("ld.acquire.gpu.u32 %0, [%1];" : "=r"(v) : "l"(p) : "memory");
    return v;
}

// ---------------------------------------------------------------------------
// Reset kernel: zero per-plane ready flags (required for every graph replay).
// ---------------------------------------------------------------------------
__global__ void __launch_bounds__(256) reset_kernel() {
    int i = blockIdx.x * 256 + threadIdx.x;
    if (i < BC) g_flag[i] = 0u;
}

// ---------------------------------------------------------------------------
// Fully fused single-pass kernel: x read EXACTLY ONCE.
// Per block (one (b,c) plane):
//  1. front-batched loads: 4x x + 4x s (8 LDG.128 in flight)
//  2. scatter x -> haloed smem tile, accumulate plane sum from registers
//  3. block-reduce -> mean; t0: publish g_y[bc] (release flag)
//  4. t0: acquire-spin on the <=4 same-batch neighbor flags (bc+-1, bc+-2),
//     compute Qf/Kf/coef/z_new. Dependency distance is 2 bids -> neighbors are
//     co-scheduled; spin is ~zero except at wave boundaries (no convoy).
//  5. depthwise 3x3 conv + s_new = s + Kf*V ; out = coef * s_new
// ---------------------------------------------------------------------------
#define TP 68   // tile pitch: 66 rows x 68 floats; (r*68 + col0) % 4 == 0

__global__ void __launch_bounds__(256)
fused_kernel(const float* __restrict__ x,
             const float* __restrict__ s,
             const float* __restrict__ z,
             const float* __restrict__ wq,
             const float* __restrict__ wk,
             const float* __restrict__ wv,
             float* __restrict__ out,
             float* __restrict__ s_new,
             float* __restrict__ z_new) {
    int bc = blockIdx.x;
    int b = bc >> 9;
    int c = bc & 511;
    size_t base = (size_t)bc * HW;
    int t = threadIdx.x;

    __shared__ float tile[66 * TP];
    __shared__ float ws[8];
    __shared__ float sKf, sCf;

    // Front-batched vector loads: 4x x + 4x s (streaming; x is single-use now).
    const float4* xp = reinterpret_cast<const float4*>(x + base);
    const float4* sp = reinterpret_cast<const float4*>(s + base);
    float4 xa[4], sv[4];
#pragma unroll
    for (int k = 0; k < 4; k++) xa[k] = __ldcs(xp + t + k * 256);
#pragma unroll
    for (int k = 0; k < 4; k++) sv[k] = __ldcs(sp + t + k * 256);

    // Zero the halo ring while loads are in flight.
    if (t < 66) { tile[t] = 0.0f; tile[65 * TP + t] = 0.0f; }
    if (t < 64) { tile[(t + 1) * TP] = 0.0f; tile[(t + 1) * TP + 65] = 0.0f; }

    // Per-channel conv weights.
    float w[9];
#pragma unroll
    for (int j = 0; j < 9; j++) w[j] = __ldg(wv + c * 9 + j);

    // Scatter x into the haloed tile AND accumulate the plane sum from regs.
    float sum = 0.0f;
#pragma unroll
    for (int k = 0; k < 4; k++) {
        int q = t + k * 256;          // float4 index 0..1023
        int p = q << 2;               // pixel
        int r = p >> 6;               // row 0..63
        int col = p & 63;             // col (multiple of 4)
        float* dst = &tile[(r + 1) * TP + col + 1];
        dst[0] = xa[k].x; dst[1] = xa[k].y; dst[2] = xa[k].z; dst[3] = xa[k].w;
        sum += (xa[k].x + xa[k].y) + (xa[k].z + xa[k].w);
    }

    // Block reduction of the plane sum.
#pragma unroll
    for (int o = 16; o > 0; o >>= 1) sum += __shfl_xor_sync(0xffffffffu, sum, o);
    if ((t & 31) == 0) ws[t >> 5] = sum;
    __syncthreads();   // covers tile scatter + ws

    if (t == 0) {
        float s2 = ws[0];
#pragma unroll
        for (int j = 1; j < 8; j++) s2 += ws[j];
        float mean = s2 * (1.0f / (float)HW);
        g_y[bc] = mean;
        st_release_gpu(&g_flag[bc], 1u);   // publish (release orders g_y before)

        // Wait for same-batch neighbors (distance <= 2 bids: co-scheduled).
#pragma unroll
        for (int j = 0; j < 5; j++) {
            if (j == 2) continue;          // own plane
            int cc = c + j - 2;
            if ((unsigned)cc < (unsigned)C) {
                const unsigned* fl = &g_flag[(b << 9) + cc];
                while (ld_acquire_gpu(fl) == 0u) __nanosleep(20);
            }
        }

        // Channel conv (k=5, SAME) -> elu+1 -> Kf, coef, z_new.
        float q = 0.0f, k = 0.0f;
#pragma unroll
        for (int j = 0; j < 5; j++) {
            int cc = c + j - 2;
            float v = 0.0f;
            if ((unsigned)cc < (unsigned)C)
                v = (cc == c) ? mean : g_y[(b << 9) + cc];
            q += __ldg(wq + j) * v;
            k += __ldg(wk + j) * v;
        }
        float Qf = (q > 0.0f) ? (q + 1.0f) : expf(q);
        float Kf = (k > 0.0f) ? (k + 1.0f) : expf(k);
        float zn = z[bc] + Kf;
        float qz = 1.0f / (Qf * (zn + 1e-6f));
        sKf = Kf;
        sCf = Qf * qz;
        z_new[bc] = zn;
    }
    __syncthreads();

    float Kf = sKf;
    float Cf = sCf;

    float4* op = reinterpret_cast<float4*>(out + base);
    float4* np = reinterpret_cast<float4*>(s_new + base);

#pragma unroll
    for (int k = 0; k < 4; k++) {
        int q = t + k * 256;
        int p = q << 2;
        int r = p >> 6;
        int col0 = p & 63;

        float a0 = 0.0f, a1 = 0.0f, a2 = 0.0f, a3 = 0.0f;
#pragma unroll
        for (int di = 0; di < 3; di++) {
            const float* rowp = &tile[(r + di) * TP + col0];
            float4 f4 = *reinterpret_cast<const float4*>(rowp);
            float2 f2 = *reinterpret_cast<const float2*>(rowp + 4);
            float w0 = w[di * 3 + 0], w1 = w[di * 3 + 1], w2 = w[di * 3 + 2];
            a0 = fmaf(w0, f4.x, fmaf(w1, f4.y, fmaf(w2, f4.z, a0)));
            a1 = fmaf(w0, f4.y, fmaf(w1, f4.z, fmaf(w2, f4.w, a1)));
            a2 = fmaf(w0, f4.z, fmaf(w1, f4.w, fmaf(w2, f2.x, a2)));
            a3 = fmaf(w0, f4.w, fmaf(w1, f2.x, fmaf(w2, f2.y, a3)));
        }

        float4 sn, ov;
        sn.x = sv[k].x + Kf * a0;
        sn.y = sv[k].y + Kf * a1;
        sn.z = sv[k].z + Kf * a2;
        sn.w = sv[k].w + Kf * a3;
        ov.x = Cf * sn.x;
        ov.y = Cf * sn.y;
        ov.z = Cf * sn.z;
        ov.w = Cf * sn.w;
        __stcs(np + q, sn);
        __stcs(op + q, ov);
    }
}

// ---------------------------------------------------------------------------
extern "C" void kernel_launch(void* const* d_in, const int* in_sizes, int n_in,
                              void* d_out, int out_size) {
    const float* x  = (const float*)d_in[0];
    const float* s  = (const float*)d_in[1];
    const float* z  = (const float*)d_in[2];
    const float* wq = (const float*)d_in[3];
    const float* wk = (const float*)d_in[4];
    const float* wv = (const float*)d_in[5];

    float* out   = (float*)d_out;                 // [BC, HW]
    float* s_new = out + (size_t)OUT_ELEMS;       // [BC, HW]
    float* z_new = s_new + (size_t)OUT_ELEMS;     // [BC]

    reset_kernel<<<BC / 256, 256>>>();
    fused_kernel<<<BC, 256>>>(x, s, z, wq, wk, wv, out, s_new, z_new);
}

// round 13
// speedup vs baseline: 1.2327x; 1.2327x over previous
#include <cuda_runtime.h>
#include <cuda_bf16.h>

// Problem shape (fixed by the dataset):
//   x : [16, 512, 64, 64] f32
//   s : [16, 512, 1, 4096] f32
//   z : [16, 1, 512, 1]   f32
//   wq: [1,1,5], wk: [1,1,5], wv: [512,1,3,3]
// Output: out [16,512,64,64], s_new [16,512,1,4096], z_new [16,1,512,1]

#define B 16
#define C 512
#define HW 4096
#define BC (B * C)            // 8192
#define OUT_ELEMS (BC * HW)   // 33554432

#define TP 68                 // tile pitch: 66 rows x 68 floats

// Cluster config: 8 CTAs x 2 planes = 16 contiguous channels per cluster.
#define NC 8

#define CLUSTER_SYNC() do { \
    asm volatile("barrier.cluster.arrive.aligned;" ::: "memory"); \
    asm volatile("barrier.cluster.wait.aligned;" ::: "memory"); \
} while (0)

__device__ __forceinline__ float dsmem_read_f32(const float* lptr, int rank) {
    unsigned la = (unsigned)__cvta_generic_to_shared(lptr);
    unsigned ra;
    float v;
    asm volatile("mapa.shared::cluster.u32 %0, %1, %2;" : "=r"(ra) : "r"(la), "r"(rank));
    asm volatile("ld.shared::cluster.f32 %0, [%1];" : "=f"(v) : "r"(ra));
    return v;
}

// ---------------------------------------------------------------------------
// Single-pass fused kernel with cluster-shared channel means.
// CTA ct handles planes bc0 = 2*ct and bc0+1. Cluster rank r = ct % 8 covers
// cluster-relative channels {2r, 2r+1} of a 16-channel group. Edge ranks
// (0,1,6,7) redundantly compute one halo-channel mean each so the 5-tap
// channel conv never crosses the cluster.
// ---------------------------------------------------------------------------
__global__ void __launch_bounds__(256) __cluster_dims__(NC, 1, 1)
fused_kernel(const float* __restrict__ x,
             const float* __restrict__ s,
             const float* __restrict__ z,
             const float* __restrict__ wq,
             const float* __restrict__ wk,
             const float* __restrict__ wv,
             float* __restrict__ out,
             float* __restrict__ s_new,
             float* __restrict__ z_new) {
    int ct = blockIdx.x;
    int r  = ct & (NC - 1);           // cluster rank
    int bc0 = ct * 2;                 // first plane
    int b  = bc0 >> 9;
    int c0 = bc0 & 511;               // channel of plane A
    int cb = c0 - 2 * r;              // cluster-base channel
    int t  = threadIdx.x;

    __shared__ __align__(16) float tileA[66 * TP];
    __shared__ __align__(16) float tileB[66 * TP];
    __shared__ float means[3];        // [0]=plane A, [1]=plane B, [2]=halo
    __shared__ float ws[16];          // warp partials: [0..7]=A, [8..15]=B
    __shared__ float ws2[8];          // warp partials: halo
    __shared__ float scr[20];         // tap partials: [p*10+j]=q, [p*10+5+j]=k
    __shared__ float sKC[4];          // KfA, CfA, KfB, CfB

    // ---- Phase 1: load both planes (8 LDG.128 in flight), scatter, sum ----
    const float4* xpA = reinterpret_cast<const float4*>(x + (size_t)bc0 * HW);
    const float4* xpB = reinterpret_cast<const float4*>(x + (size_t)(bc0 + 1) * HW);
    float4 xa[4], xb[4];
#pragma unroll
    for (int k = 0; k < 4; k++) xa[k] = __ldcs(xpA + t + k * 256);
#pragma unroll
    for (int k = 0; k < 4; k++) xb[k] = __ldcs(xpB + t + k * 256);

    // Zero both halo rings while loads are in flight.
    if (t < 66) {
        tileA[t] = 0.0f; tileA[65 * TP + t] = 0.0f;
        tileB[t] = 0.0f; tileB[65 * TP + t] = 0.0f;
    }
    if (t < 64) {
        tileA[(t + 1) * TP] = 0.0f; tileA[(t + 1) * TP + 65] = 0.0f;
        tileB[(t + 1) * TP] = 0.0f; tileB[(t + 1) * TP + 65] = 0.0f;
    }

    float sumA = 0.0f, sumB = 0.0f;
#pragma unroll
    for (int k = 0; k < 4; k++) {
        int q = t + k * 256;
        int p = q << 2;
        int row = p >> 6;
        int col = p & 63;
        float* dA = &tileA[(row + 1) * TP + col + 1];
        dA[0] = xa[k].x; dA[1] = xa[k].y; dA[2] = xa[k].z; dA[3] = xa[k].w;
        sumA += (xa[k].x + xa[k].y) + (xa[k].z + xa[k].w);
        float* dB = &tileB[(row + 1) * TP + col + 1];
        dB[0] = xb[k].x; dB[1] = xb[k].y; dB[2] = xb[k].z; dB[3] = xb[k].w;
        sumB += (xb[k].x + xb[k].y) + (xb[k].z + xb[k].w);
    }

    // ---- Halo plane (edge ranks only): one extra plane-mean, no scatter ----
    bool edge = (r < 2) || (r >= NC - 2);
    int mh = (r < 2) ? (r - 2) : (r + 10);     // r0->-2, r1->-1, r6->16, r7->17
    int chH = cb + mh;
    bool validH = edge && ((unsigned)chH < (unsigned)C);
    float sumH = 0.0f;
    if (validH) {
        const float4* xpH =
            reinterpret_cast<const float4*>(x + (size_t)((b << 9) + chH) * HW);
#pragma unroll
        for (int k = 0; k < 4; k++) {
            float4 v = __ldg(xpH + t + k * 256);   // read twice overall: default
            sumH += (v.x + v.y) + (v.z + v.w);
        }
    }

    // ---- Block reductions ----
#pragma unroll
    for (int o = 16; o > 0; o >>= 1) {
        sumA += __shfl_xor_sync(0xffffffffu, sumA, o);
        sumB += __shfl_xor_sync(0xffffffffu, sumB, o);
        sumH += __shfl_xor_sync(0xffffffffu, sumH, o);
    }
    if ((t & 31) == 0) {
        ws[t >> 5] = sumA;
        ws[8 + (t >> 5)] = sumB;
        ws2[t >> 5] = sumH;
    }
    __syncthreads();
    if (t == 0) {
        float sA = 0.0f, sB = 0.0f, sH = 0.0f;
#pragma unroll
        for (int j = 0; j < 8; j++) { sA += ws[j]; sB += ws[8 + j]; sH += ws2[j]; }
        means[0] = sA * (1.0f / (float)HW);
        means[1] = sB * (1.0f / (float)HW);
        means[2] = validH ? sH * (1.0f / (float)HW) : 0.0f;
    }

    // ---- Cluster sync #1: all means published cluster-wide ----
    CLUSTER_SYNC();

    // ---- Gather 5 taps per plane via DSMEM (10 threads in parallel) ----
    if (t < 5 || (t >= 32 && t < 37)) {
        int plane = (t >= 32) ? 1 : 0;
        int j = plane ? (t - 32) : t;            // tap 0..4
        int mm = (2 * r + plane) + j - 2;        // cluster-rel channel, [-2,17]
        int rank, slot;
        if (mm < 0)       { rank = mm + 2;  slot = 2; }
        else if (mm > 15) { rank = mm - 10; slot = 2; }
        else              { rank = mm >> 1; slot = mm & 1; }
        float v = 0.0f;
        if ((unsigned)(cb + mm) < (unsigned)C)
            v = dsmem_read_f32(&means[slot], rank);
        scr[plane * 10 + j]     = __ldg(wq + j) * v;
        scr[plane * 10 + 5 + j] = __ldg(wk + j) * v;
    }
    __syncthreads();

    if (t == 0 || t == 32) {
        int plane = t >> 5;
        float q = 0.0f, k = 0.0f;
#pragma unroll
        for (int j = 0; j < 5; j++) {
            q += scr[plane * 10 + j];
            k += scr[plane * 10 + 5 + j];
        }
        float Qf = (q > 0.0f) ? (q + 1.0f) : expf(q);
        float Kf = (k > 0.0f) ? (k + 1.0f) : expf(k);
        float zn = z[bc0 + plane] + Kf;
        float qz = 1.0f / (Qf * (zn + 1e-6f));
        sKC[plane * 2]     = Kf;
        sKC[plane * 2 + 1] = Qf * qz;
        z_new[bc0 + plane] = zn;
    }

    // ---- Cluster sync #2: all DSMEM reads done -> safe to exit later; also
    //      acts as the block barrier making sKC visible. ----
    CLUSTER_SYNC();

    // ---- Epilogue: conv + s_new/out for both planes ----
#pragma unroll
    for (int plane = 0; plane < 2; plane++) {
        int bc = bc0 + plane;
        size_t base = (size_t)bc * HW;
        const float* tile = plane ? tileB : tileA;
        float Kf = sKC[plane * 2];
        float Cf = sKC[plane * 2 + 1];

        float w[9];
#pragma unroll
        for (int j = 0; j < 9; j++) w[j] = __ldg(wv + bc % C * 9 + j);

        const float4* sp = reinterpret_cast<const float4*>(s + base);
        float4* op = reinterpret_cast<float4*>(out + base);
        float4* np = reinterpret_cast<float4*>(s_new + base);

#pragma unroll
        for (int k = 0; k < 4; k++) {
            int q = t + k * 256;
            int p = q << 2;
            int row = p >> 6;
            int col0 = p & 63;

            float4 sv = __ldcs(sp + q);

            float a0 = 0.0f, a1 = 0.0f, a2 = 0.0f, a3 = 0.0f;
#pragma unroll
            for (int di = 0; di < 3; di++) {
                const float* rowp = &tile[(row + di) * TP + col0];
                float4 f4 = *reinterpret_cast<const float4*>(rowp);
                float2 f2 = *reinterpret_cast<const float2*>(rowp + 4);
                float w0 = w[di * 3 + 0], w1 = w[di * 3 + 1], w2 = w[di * 3 + 2];
                a0 = fmaf(w0, f4.x, fmaf(w1, f4.y, fmaf(w2, f4.z, a0)));
                a1 = fmaf(w0, f4.y, fmaf(w1, f4.z, fmaf(w2, f4.w, a1)));
                a2 = fmaf(w0, f4.z, fmaf(w1, f4.w, fmaf(w2, f2.x, a2)));
                a3 = fmaf(w0, f4.w, fmaf(w1, f2.x, fmaf(w2, f2.y, a3)));
            }

            float4 sn, ov;
            sn.x = sv.x + Kf * a0;
            sn.y = sv.y + Kf * a1;
            sn.z = sv.z + Kf * a2;
            sn.w = sv.w + Kf * a3;
            ov.x = Cf * sn.x;
            ov.y = Cf * sn.y;
            ov.z = Cf * sn.z;
            ov.w = Cf * sn.w;
            __stcs(np + q, sn);
            __stcs(op + q, ov);
        }
    }
}

// ---------------------------------------------------------------------------
extern "C" void kernel_launch(void* const* d_in, const int* in_sizes, int n_in,
                              void* d_out, int out_size) {
    const float* x  = (const float*)d_in[0];
    const float* s  = (const float*)d_in[1];
    const float* z  = (const float*)d_in[2];
    const float* wq = (const float*)d_in[3];
    const float* wk = (const float*)d_in[4];
    const float* wv = (const float*)d_in[5];

    float* out   = (float*)d_out;                 // [BC, HW]
    float* s_new = out + (size_t)OUT_ELEMS;       // [BC, HW]
    float* z_new = s_new + (size_t)OUT_ELEMS;     // [BC]

    fused_kernel<<<BC / 2, 256>>>(x, s, z, wq, wk, wv, out, s_new, z_new);
}